// round 10
// baseline (speedup 1.0000x reference)
#include <cuda_runtime.h>
#include <cuda_bf16.h>
#include <cstdint>

// ShiftKernelMaker: per (b,c) 7x7 slice, emit one-hot (==max) mask.
// Input : float32 [128, 4096, 7, 7]  -> flat 524288 slices x 49 floats
// Output: float32 [524288, 1, 7, 7]  -> same flat layout
//
// R8 -> R9 (resubmit; prior round was an infra failure): wall time pinned
// at ~36.9us (205.5 MB / 36.9us = 5.57 TB/s steady-state DRAM) for two
// different kernels -> near the mixed r/w DRAM floor. Squeeze remaining
// kernel-side slack with depth-2 prefetch in one-shot blocks: each
// 64-thread block owns TWO ADJACENT 12.5KB tiles, issues both TMA loads
// up-front, computes t0 while t1 arrives, stores t0 async under compute of
// t1. 25KB contiguous read burst per block, ~18 loads in flight/SM, no
// pipeline serialization (R7's mistake).

constexpr int KK = 49;                 // 7*7
constexpr int SLICES_PER_TILE = 64;    // one slice per thread
constexpr int THREADS = 64;
constexpr int TILE_FLOATS = SLICES_PER_TILE * KK;    // 3136
constexpr int TILE_BYTES  = TILE_FLOATS * 4;         // 12544 (16B multiple)
constexpr int TILES_PER_BLOCK = 2;

__device__ __forceinline__ uint32_t smem_u32(const void* p) {
    uint32_t a;
    asm("{ .reg .u64 t; cvta.to.shared.u64 t, %1; cvt.u32.u64 %0, t; }"
        : "=r"(a) : "l"(p));
    return a;
}

__device__ __forceinline__ void mbar_wait0(uint32_t mbar) {
    uint32_t done;
    asm volatile(
        "{\n\t"
        ".reg .pred p;\n\t"
        "mbarrier.try_wait.parity.acquire.cta.shared::cta.b64 p, [%1], 0;\n\t"
        "selp.b32 %0, 1, 0, p;\n\t"
        "}" : "=r"(done) : "r"(mbar) : "memory");
    if (!done) {
        asm volatile(
            "{\n\t"
            ".reg .pred P1;\n\t"
            "WAIT_LOOP_%=:\n\t"
            "mbarrier.try_wait.parity.acquire.cta.shared::cta.b64 P1, [%0], 0, 0x989680;\n\t"
            "@P1 bra.uni WAIT_DONE_%=;\n\t"
            "bra.uni WAIT_LOOP_%=;\n\t"
            "WAIT_DONE_%=:\n\t"
            "}" :: "r"(mbar) : "memory");
    }
}

__global__ __launch_bounds__(THREADS)
void shift_mask_kernel(const float* __restrict__ in, float* __restrict__ out) {
    __shared__ alignas(16) float tile0[TILE_FLOATS];
    __shared__ alignas(16) float tile1[TILE_FLOATS];
    __shared__ alignas(8)  uint64_t mbar[2];

    const size_t base = (size_t)blockIdx.x * (TILES_PER_BLOCK * TILE_FLOATS);
    float* buf[2] = { tile0, tile1 };
    const uint32_t s_buf[2]  = { smem_u32(tile0), smem_u32(tile1) };
    const uint32_t s_mbar[2] = { smem_u32(&mbar[0]), smem_u32(&mbar[1]) };

    if (threadIdx.x == 0) {
        asm volatile("mbarrier.init.shared.b64 [%0], 1;" :: "r"(s_mbar[0]) : "memory");
        asm volatile("mbarrier.init.shared.b64 [%0], 1;" :: "r"(s_mbar[1]) : "memory");
    }
    __syncthreads();

    // ---- issue BOTH tile loads up-front (25KB contiguous read burst) ----
    if (threadIdx.x == 0) {
        #pragma unroll
        for (int t = 0; t < TILES_PER_BLOCK; t++) {
            asm volatile("mbarrier.arrive.expect_tx.shared.b64 _, [%0], %1;"
                         :: "r"(s_mbar[t]), "r"(TILE_BYTES) : "memory");
            asm volatile("cp.async.bulk.shared::cluster.global.mbarrier::complete_tx::bytes"
                         " [%0], [%1], %2, [%3];"
                         :: "r"(s_buf[t]), "l"(in + base + (size_t)t * TILE_FLOATS),
                            "r"(TILE_BYTES), "r"(s_mbar[t]) : "memory");
        }
    }

    // ---- process tile t: wait, compute in place, async store ----
    #pragma unroll
    for (int t = 0; t < TILES_PER_BLOCK; t++) {
        mbar_wait0(s_mbar[t]);

        // per-thread row max + in-place mask.
        // smem index = tid*49 + i : 49 odd => conflict-free bank permutation.
        {
            float* row = buf[t] + threadIdx.x * KK;
            float mx = row[0];
            #pragma unroll
            for (int i = 1; i < KK; i++) mx = fmaxf(mx, row[i]);
            #pragma unroll
            for (int i = 0; i < KK; i++) row[i] = (row[i] == mx) ? 1.0f : 0.0f;
        }
        __syncthreads();

        asm volatile("fence.proxy.async.shared::cta;" ::: "memory");
        if (threadIdx.x == 0) {
            asm volatile("cp.async.bulk.global.shared::cta.bulk_group [%0], [%1], %2;"
                         :: "l"(out + base + (size_t)t * TILE_FLOATS), "r"(s_buf[t]),
                            "r"(TILE_BYTES) : "memory");
            asm volatile("cp.async.bulk.commit_group;" ::: "memory");
        }
    }

    // ---- drain outstanding stores before CTA exit ----
    if (threadIdx.x == 0) {
        asm volatile("cp.async.bulk.wait_group 0;" ::: "memory");
    }
}

extern "C" void kernel_launch(void* const* d_in, const int* in_sizes, int n_in,
                              void* d_out, int out_size) {
    const float* in = (const float*)d_in[0];
    float* out = (float*)d_out;

    const int n_elems  = in_sizes[0];                          // 25690112
    const int n_slices = n_elems / KK;                         // 524288
    const int grid = n_slices / (SLICES_PER_TILE * TILES_PER_BLOCK);  // 4096 (exact)

    shift_mask_kernel<<<grid, THREADS>>>(in, out);
}